// round 9
// baseline (speedup 1.0000x reference)
#include <cuda_runtime.h>

// ---------------------------------------------------------------------------
// AutoregressiveGRUWithAttention  (B=1024, L=64, T=128, IN=13, H=64, OUT=13)
//
// R8: 128 blocks x 128 threads. Each thread owns hidden channel j for FOUR
// batches (2 groups x 64 channels) -> weight smem reads amortized 4x (the
// measured bottleneck was the shared-memory crossbar at 62%, dominated by
// Whh/Wa row reads duplicated across batch-groups).
// All 64-wide dot products use packed fma.rn.f32x2 (2 MACs/instr), with
// weights and h loaded directly as ulonglong2 (LDS.128 = 2 f32x2 operands).
// Wih rows + biases live in registers (loop-invariant). x preloaded to smem.
// Online-softmax attention as in R7 (bit-equivalent math to reference).
// ---------------------------------------------------------------------------

typedef unsigned long long ull;

namespace {
constexpr int L_   = 64;
constexpr int T_   = 128;
constexpr int IN_  = 13;
constexpr int H_   = 64;
constexpr int H3_  = 192;
constexpr int OUT_ = 13;
constexpr int WP_  = 68;     // padded row stride (floats): conflict-free LDS.128
constexpr int NB_  = 8;      // batches per block
constexpr int THREADS_ = 128;
constexpr int BLOCKS_  = 128;
constexpr int XPB_ = L_ * IN_;      // 832 floats of x per batch

// shared layout (floats)
constexpr int SM_WHH = 0;                    // [192][68]
constexpr int SM_WA  = SM_WHH + H3_ * WP_;   // [64][68]
constexpr int SM_WF  = SM_WA  + H_  * WP_;   // [16][68] (13 used)
constexpr int SM_H   = SM_WF  + 16  * WP_;   // [8][68]
constexpr int SM_O   = SM_H   + NB_ * WP_;   // [8][68]
constexpr int SM_NIN = SM_O   + NB_ * WP_;   // [8][16]
constexpr int SM_X   = SM_NIN + NB_ * 16;    // [8][832]
constexpr int SM_FLOATS = SM_X + NB_ * XPB_;
constexpr int SMEM_BYTES = SM_FLOATS * 4;    // ~105.5 KB
}

__device__ __forceinline__ ull fma2_(ull a, ull b, ull c) {
    ull d;
    asm("fma.rn.f32x2 %0, %1, %2, %3;" : "=l"(d) : "l"(a), "l"(b), "l"(c));
    return d;
}
__device__ __forceinline__ float hsum2_(ull a) {
    unsigned lo, hi;
    asm("mov.b64 {%0, %1}, %2;" : "=r"(lo), "=r"(hi) : "l"(a));
    return __uint_as_float(lo) + __uint_as_float(hi);
}
__device__ __forceinline__ float sigmoid_(float a) {
    return __fdividef(1.f, 1.f + __expf(-a));
}
__device__ __forceinline__ float tanh_(float a) {
    float c  = fminf(fmaxf(a, -15.f), 15.f);
    float e2 = __expf(2.f * c);
    return __fdividef(e2 - 1.f, e2 + 1.f);
}

__global__ void __launch_bounds__(THREADS_, 1)
gru_attn_kernel(const float* __restrict__ x, const int* __restrict__ lengths,
                const float* __restrict__ Wih, const float* __restrict__ Whh,
                const float* __restrict__ bih, const float* __restrict__ bhh,
                const float* __restrict__ Wf,  const float* __restrict__ bf,
                const float* __restrict__ Wa,  const float* __restrict__ ba,
                float* __restrict__ out)
{
    extern __shared__ float sm[];
    float* sWhh = sm + SM_WHH;
    float* sWa  = sm + SM_WA;
    float* sWf  = sm + SM_WF;
    float* sh   = sm + SM_H;
    float* so   = sm + SM_O;
    float* snin = sm + SM_NIN;
    float* sx   = sm + SM_X;

    const int tid = threadIdx.x;
    const int j   = tid & 63;        // hidden channel
    const int g   = tid >> 6;        // batch group 0..1 (4 batches each)
    const int b0  = blockIdx.x * NB_;
    const int bq  = 4 * g;           // first local batch of this thread

    // ---- stage weights (padded rows) + all of x for this block's 8 batches
    for (int idx = tid; idx < H3_ * H_; idx += THREADS_) {
        int r = idx >> 6, c = idx & 63;
        sWhh[r * WP_ + c] = Whh[idx];
    }
    for (int idx = tid; idx < H_ * H_; idx += THREADS_) {
        int r = idx >> 6, c = idx & 63;
        sWa[r * WP_ + c] = Wa[idx];
    }
    for (int idx = tid; idx < OUT_ * H_; idx += THREADS_) {
        int r = idx >> 6, c = idx & 63;
        sWf[r * WP_ + c] = Wf[idx];
    }
    {   // x: contiguous [8*832] floats, copy as float4
        const float4* xg = (const float4*)(x + (size_t)b0 * XPB_);
        float4* xs = (float4*)sx;
        for (int idx = tid; idx < NB_ * XPB_ / 4; idx += THREADS_) xs[idx] = xg[idx];
    }
    for (int idx = tid; idx < NB_ * WP_; idx += THREADS_) { sh[idx] = 0.f; so[idx] = 0.f; }

    // loop-invariant per-thread registers
    float wir[IN_], wiz[IN_], win[IN_];
    #pragma unroll
    for (int i = 0; i < IN_; ++i) {
        wir[i] = Wih[j * IN_ + i];
        wiz[i] = Wih[(64 + j) * IN_ + i];
        win[i] = Wih[(128 + j) * IN_ + i];
    }
    const float bir = bih[j], biz = bih[64 + j], bin = bih[128 + j];
    const float bhr = bhh[j], bhz = bhh[64 + j], bhn = bhh[128 + j];
    const float bav = ba[j];
    const float bfv = (j < OUT_) ? bf[j] : 0.f;

    int len_[4];
    #pragma unroll
    for (int b = 0; b < 4; ++b) len_[b] = lengths[b0 + bq + b];

    __syncthreads();

    const ulonglong2* whr = (const ulonglong2*)(sWhh + j * WP_);
    const ulonglong2* whz = (const ulonglong2*)(sWhh + (64 + j) * WP_);
    const ulonglong2* whn = (const ulonglong2*)(sWhh + (128 + j) * WP_);
    const ulonglong2* war = (const ulonglong2*)(sWa + j * WP_);
    const ulonglong2* wfr = (const ulonglong2*)(sWf + j * WP_);   // valid if j<13
    const ulonglong2* hb[4];
    const ulonglong2* ob[4];
    #pragma unroll
    for (int b = 0; b < 4; ++b) {
        hb[b] = (const ulonglong2*)(sh + (bq + b) * WP_);
        ob[b] = (const ulonglong2*)(so + (bq + b) * WP_);
    }

    // =======================  ENCODER  =======================
    for (int t = 0; t < L_; ++t) {
        // gi = Wih @ x_t + bih   (x from smem, weights in regs)
        float gr[4], gz[4], gn[4];
        #pragma unroll
        for (int b = 0; b < 4; ++b) {
            const float* xb = sx + (bq + b) * XPB_ + t * IN_;
            float ar = bir, az = biz, an = bin;
            #pragma unroll
            for (int i = 0; i < IN_; ++i) {
                float xv = xb[i];
                ar += wir[i] * xv; az += wiz[i] * xv; an += win[i] * xv;
            }
            gr[b] = ar; gz[b] = az; gn[b] = an;
        }
        // gh = Whh @ h + bhh  (packed f32x2)
        ull ar_[4] = {0,0,0,0}, az_[4] = {0,0,0,0}, an_[4] = {0,0,0,0};
        #pragma unroll
        for (int q = 0; q < 16; ++q) {
            ulonglong2 wr = whr[q], wz = whz[q], wn = whn[q];
            #pragma unroll
            for (int b = 0; b < 4; ++b) {
                ulonglong2 hq = hb[b][q];
                ar_[b] = fma2_(wr.x, hq.x, ar_[b]); ar_[b] = fma2_(wr.y, hq.y, ar_[b]);
                az_[b] = fma2_(wz.x, hq.x, az_[b]); az_[b] = fma2_(wz.y, hq.y, az_[b]);
                an_[b] = fma2_(wn.x, hq.x, an_[b]); an_[b] = fma2_(wn.y, hq.y, an_[b]);
            }
        }
        float hv[4];
        #pragma unroll
        for (int b = 0; b < 4; ++b) {
            float hr = bhr + hsum2_(ar_[b]);
            float hz = bhz + hsum2_(az_[b]);
            float hn = bhn + hsum2_(an_[b]);
            float r = sigmoid_(gr[b] + hr);
            float z = sigmoid_(gz[b] + hz);
            float n = tanh_(gn[b] + r * hn);
            float hp = sh[(bq + b) * WP_ + j];
            hv[b] = (t < len_[b]) ? ((1.f - z) * n + z * hp) : hp;
        }
        __syncthreads();                // all reads of old h done
        #pragma unroll
        for (int b = 0; b < 4; ++b) sh[(bq + b) * WP_ + j] = hv[b];
        __syncthreads();                // new h visible
    }

    // outs[-1] nonzero only when lengths == L (then equals final h)
    #pragma unroll
    for (int b = 0; b < 4; ++b)
        so[(bq + b) * WP_ + j] = (len_[b] == L_) ? sh[(bq + b) * WP_ + j] : 0.f;
    __syncthreads();

    // nin = outs[-1] @ Wf^T + bf
    if (j < OUT_) {
        ull ya[4] = {0,0,0,0};
        #pragma unroll
        for (int q = 0; q < 16; ++q) {
            ulonglong2 w = wfr[q];
            #pragma unroll
            for (int b = 0; b < 4; ++b) {
                ulonglong2 oq = ob[b][q];
                ya[b] = fma2_(w.x, oq.x, ya[b]);
                ya[b] = fma2_(w.y, oq.y, ya[b]);
            }
        }
        #pragma unroll
        for (int b = 0; b < 4; ++b)
            snin[(bq + b) * 16 + j] = bfv + hsum2_(ya[b]);
    }
    __syncthreads();

    // =======================  DECODER  =======================
    float m_[4], s_[4], a_[4];
    #pragma unroll
    for (int b = 0; b < 4; ++b) { m_[b] = -1e30f; s_[b] = 0.f; a_[b] = 0.f; }

    for (int t = 0; t < T_; ++t) {
        // gi = Wih @ y_prev + bih
        float gr[4], gz[4], gn[4];
        #pragma unroll
        for (int b = 0; b < 4; ++b) {
            const float* nb = snin + (bq + b) * 16;
            float ar = bir, az = biz, an = bin;
            #pragma unroll
            for (int i = 0; i < IN_; ++i) {
                float nv = nb[i];
                ar += wir[i] * nv; az += wiz[i] * nv; an += win[i] * nv;
            }
            gr[b] = ar; gz[b] = az; gn[b] = an;
        }
        // gh = Whh @ h + bhh
        ull ar_[4] = {0,0,0,0}, az_[4] = {0,0,0,0}, an_[4] = {0,0,0,0};
        #pragma unroll
        for (int q = 0; q < 16; ++q) {
            ulonglong2 wr = whr[q], wz = whz[q], wn = whn[q];
            #pragma unroll
            for (int b = 0; b < 4; ++b) {
                ulonglong2 hq = hb[b][q];
                ar_[b] = fma2_(wr.x, hq.x, ar_[b]); ar_[b] = fma2_(wr.y, hq.y, ar_[b]);
                az_[b] = fma2_(wz.x, hq.x, az_[b]); az_[b] = fma2_(wz.y, hq.y, az_[b]);
                an_[b] = fma2_(wn.x, hq.x, an_[b]); an_[b] = fma2_(wn.y, hq.y, an_[b]);
            }
        }
        float hne[4], ov[4];
        #pragma unroll
        for (int b = 0; b < 4; ++b) {
            float hr = bhr + hsum2_(ar_[b]);
            float hz = bhz + hsum2_(az_[b]);
            float hn = bhn + hsum2_(an_[b]);
            float r = sigmoid_(gr[b] + hr);
            float z = sigmoid_(gz[b] + hz);
            float n = tanh_(gn[b] + r * hn);
            float hp = sh[(bq + b) * WP_ + j];
            hne[b] = (1.f - z) * n + z * hp;
            float att = (t == 0) ? 0.f : __fdividef(a_[b], s_[b]);
            ov[b] = hne[b] + att;
        }
        __syncthreads();                // (A) all reads of old sh/so/snin done
        #pragma unroll
        for (int b = 0; b < 4; ++b) {
            sh[(bq + b) * WP_ + j] = hne[b];
            so[(bq + b) * WP_ + j] = ov[b];
        }
        __syncthreads();                // (B) new h/o visible

        // logits l[j] = Wa[j,:] . o + ba[j]
        ull la[4] = {0,0,0,0};
        #pragma unroll
        for (int q = 0; q < 16; ++q) {
            ulonglong2 w = war[q];
            #pragma unroll
            for (int b = 0; b < 4; ++b) {
                ulonglong2 oq = ob[b][q];
                la[b] = fma2_(w.x, oq.x, la[b]);
                la[b] = fma2_(w.y, oq.y, la[b]);
            }
        }

        // y = o @ Wf^T + bf  -> output + next decoder input
        if (j < OUT_) {
            ull ya[4] = {0,0,0,0};
            #pragma unroll
            for (int q = 0; q < 16; ++q) {
                ulonglong2 w = wfr[q];
                #pragma unroll
                for (int b = 0; b < 4; ++b) {
                    ulonglong2 oq = ob[b][q];
                    ya[b] = fma2_(w.x, oq.x, ya[b]);
                    ya[b] = fma2_(w.y, oq.y, ya[b]);
                }
            }
            #pragma unroll
            for (int b = 0; b < 4; ++b) {
                float y = bfv + hsum2_(ya[b]);
                out[((size_t)(b0 + bq + b) * T_ + t) * OUT_ + j] = y;
                snin[(bq + b) * 16 + j] = y;
            }
        }

        // online softmax fold of entry t (buf[t] = o)
        #pragma unroll
        for (int b = 0; b < 4; ++b) {
            float l = bav + hsum2_(la[b]);
            float mn = fmaxf(m_[b], l);
            float c = __expf(m_[b] - mn), e = __expf(l - mn);
            s_[b] = s_[b] * c + e;
            a_[b] = a_[b] * c + e * ov[b];
            m_[b] = mn;
        }
        __syncthreads();                // (C) snin (y) visible for next step
    }
}

extern "C" void kernel_launch(void* const* d_in, const int* in_sizes, int n_in,
                              void* d_out, int out_size) {
    const float* xp   = nullptr;
    const int*   lenp = nullptr;
    const float *Wihp = nullptr, *Whhp = nullptr, *bihp = nullptr, *bhhp = nullptr;
    const float *Wfp = nullptr, *bfp = nullptr, *Wap = nullptr, *bap = nullptr;

    for (int i = 0; i < n_in; ++i) {
        switch (in_sizes[i]) {
            case 1024 * 64 * 13: xp   = (const float*)d_in[i]; break;
            case 1024:           lenp = (const int*)d_in[i];   break;
            case 192 * 13:       Wihp = (const float*)d_in[i]; break;
            case 192 * 64:       Whhp = (const float*)d_in[i]; break;
            case 192:
                if (!bihp) bihp = (const float*)d_in[i];
                else       bhhp = (const float*)d_in[i];
                break;
            case 13 * 64:        Wfp  = (const float*)d_in[i]; break;
            case 13:             bfp  = (const float*)d_in[i]; break;
            case 64 * 64:        Wap  = (const float*)d_in[i]; break;
            case 64:             bap  = (const float*)d_in[i]; break;
            default: break;   // output_length scalar -> T=128 hardcoded
        }
    }

    cudaFuncSetAttribute(gru_attn_kernel,
                         cudaFuncAttributeMaxDynamicSharedMemorySize, SMEM_BYTES);

    gru_attn_kernel<<<BLOCKS_, THREADS_, SMEM_BYTES>>>(
        xp, lenp, Wihp, Whhp, bihp, bhhp, Wfp, bfp, Wap, bap, (float*)d_out);
}